// round 3
// baseline (speedup 1.0000x reference)
#include <cuda_runtime.h>

#define F 1024
#define MROWS 128      // number of comp rows (= B)
#define KDIM 4096      // 4 * F
#define SPLITK 4
#define KCHUNK (KDIM / SPLITK)   // 1024

// Scratch (no cudaMalloc allowed): split-K partials + combined comp matrix.
__device__ float g_part[SPLITK][MROWS][F];   // 2 MB
__device__ float g_comp[MROWS][F];           // 0.5 MB

// ---------------------------------------------------------------------------
// Kernel 1: split-K fp32 GEMM   comp_part[kz] = X[128,4096] @ W[4096,1024]
//   X = memory + 512*F  (row-major 128x4096: memory rows 512..1023 flattened)
//   W = kernel flattened (4096 x 1024 row-major)
// Block tile 32x64, BK=32, 256 threads, 2x4 micro-tile per thread.
// Grid: (N/64=16, M/32=4, SPLITK=4) = 256 blocks.
// ---------------------------------------------------------------------------
__global__ __launch_bounds__(256) void OSAR_gemm(const float* __restrict__ X,
                                                 const float* __restrict__ W) {
    __shared__ float As[32][32];
    __shared__ float Bs[32][64];

    const int bn = blockIdx.x;          // 0..15  (cols of 64)
    const int bm = blockIdx.y;          // 0..3   (rows of 32)
    const int kz = blockIdx.z;          // 0..3   (K chunk)
    const int tid = threadIdx.x;
    const int tx = tid & 15;            // col group (4 cols each)
    const int ty = tid >> 4;            // row group (2 rows each)

    const float* Xb = X + bm * 32 * KDIM + kz * KCHUNK;
    const float* Wb = W + (size_t)kz * KCHUNK * F + bn * 64;

    // A-load map: thread t -> row t>>3, float4 slot t&7 (exactly 1 float4/thread)
    const int ar = tid >> 3, ac4 = tid & 7;

    float acc[8] = {0.f, 0.f, 0.f, 0.f, 0.f, 0.f, 0.f, 0.f};

    for (int kk = 0; kk < KCHUNK; kk += 32) {
        // load A tile 32x32 (1 float4 per thread)
        float4 av = *(const float4*)(Xb + ar * KDIM + kk + ac4 * 4);
        *(float4*)&As[ar][ac4 * 4] = av;
        // load B tile 32x64 (2 float4 per thread)
#pragma unroll
        for (int i = 0; i < 2; i++) {
            int idx = tid + i * 256;
            int br = idx >> 4, bc4 = idx & 15;
            float4 bv = *(const float4*)(Wb + (size_t)(kk + br) * F + bc4 * 4);
            *(float4*)&Bs[br][bc4 * 4] = bv;
        }
        __syncthreads();
#pragma unroll
        for (int k = 0; k < 32; k++) {
            float a0 = As[ty * 2][k];
            float a1 = As[ty * 2 + 1][k];
            float4 b = *(float4*)&Bs[k][tx * 4];
            acc[0] += a0 * b.x; acc[1] += a0 * b.y;
            acc[2] += a0 * b.z; acc[3] += a0 * b.w;
            acc[4] += a1 * b.x; acc[5] += a1 * b.y;
            acc[6] += a1 * b.z; acc[7] += a1 * b.w;
        }
        __syncthreads();
    }

    const int row0 = bm * 32 + ty * 2;
    const int col  = bn * 64 + tx * 4;
    float* out = &g_part[kz][row0][col];
    *(float4*)out       = make_float4(acc[0], acc[1], acc[2], acc[3]);
    *(float4*)(out + F) = make_float4(acc[4], acc[5], acc[6], acc[7]);
}

// ---------------------------------------------------------------------------
// Kernel 2: combine split-K partials + bias -> g_comp
// ---------------------------------------------------------------------------
__global__ __launch_bounds__(256) void OSAR_combine(const float* __restrict__ bias) {
    int i = blockIdx.x * 256 + threadIdx.x;   // < 128*1024
    const float* p = &g_part[0][0][0];
    float v = p[i] + p[(size_t)MROWS * F + i] + p[(size_t)2 * MROWS * F + i] +
              p[(size_t)3 * MROWS * F + i] + bias[i & (F - 1)];
    (&g_comp[0][0])[i] = v;
}

// ---------------------------------------------------------------------------
// Kernel 3: gather-copy of the 128 x 1024 x 1024 output.
// One block per output row (4 KB), 256 threads x float4. All source rows are
// L2-resident (memory 4MB + inputs 2MB + comp 0.5MB); writes are the HBM floor.
//
// Row source map (derived from the unrolled scan):
//   m < 511-b          -> memory[m + b + 1]
//   511-b <= m < 512   -> comp[m - (511-b)]
//   m'=m-512 < 508-4b  -> memory[516 + 4b + m']
//   else               -> inputs_flat[m' - (508-4b)]
// ---------------------------------------------------------------------------
__global__ __launch_bounds__(256) void OSAR_copy(const float* __restrict__ inputs,
                                                 const float* __restrict__ memory,
                                                 float* __restrict__ out) {
    const int row = blockIdx.x;        // 0 .. 128*1024-1
    const int b = row >> 10;
    const int m = row & 1023;

    const float* src;
    if (m < 512) {
        const int thresh = 511 - b;
        if (m < thresh) src = memory + (size_t)(m + b + 1) * F;
        else            src = &g_comp[m - thresh][0];
    } else {
        const int mp = m - 512;
        const int thresh = 508 - 4 * b;
        if (mp < thresh) src = memory + (size_t)(516 + 4 * b + mp) * F;
        else             src = inputs + (size_t)(mp - thresh) * F;
    }

    float4 v = ((const float4*)src)[threadIdx.x];
    ((float4*)(out + (size_t)row * F))[threadIdx.x] = v;
}

// ---------------------------------------------------------------------------
extern "C" void kernel_launch(void* const* d_in, const int* in_sizes, int n_in,
                              void* d_out, int out_size) {
    const float* inputs = (const float*)d_in[0];   // (128, 4, 1024)
    const float* memory = (const float*)d_in[1];   // (1024, 1024)
    const float* kern   = (const float*)d_in[2];   // (4, 1024, 1024)
    const float* bias   = (const float*)d_in[3];   // (1024,)
    float* out = (float*)d_out;                    // (128, 1024, 1024)

    dim3 ggemm(16, 4, SPLITK);
    OSAR_gemm<<<ggemm, 256>>>(memory + 512 * F, kern);
    OSAR_combine<<<(MROWS * F) / 256, 256>>>(bias);
    OSAR_copy<<<128 * 1024, 256>>>(inputs, memory, out);
}